// round 3
// baseline (speedup 1.0000x reference)
#include <cuda_runtime.h>
#include <cuda_fp16.h>
#include <cstdint>

// ---------------------------------------------------------------------------
// out[b,s,o] = sum_i x[b,s,i] * (nf4[codes][o,i] * scale[o]) + bias[o]
// M = 8192, N = 4096, K = 4096, fp32 in/out.
// Plain sm_103 target (no tcgen05). HMMA m16n8k16 + ldmatrix + cp.async.
// R3: warp tile 32x64 -> 64x64 (smem bytes/HMMA 192 -> 128), CTA tile
// 128x128 -> 128x256 (L2 traffic 4.3 -> 3.2 GB), 4-stage pipeline.
// ---------------------------------------------------------------------------

static constexpr int M_TOTAL = 8192;
static constexpr int N_TOTAL = 4096;
static constexpr int K_TOTAL = 4096;

static constexpr int BM = 128;
static constexpr int BN = 256;
static constexpr int BK = 64;            // 64 halfs = 128 B/row (SW128)
static constexpr int STAGES = 4;
static constexpr int KITERS = K_TOTAL / BK;  // 64

static constexpr int A_BYTES = BM * 128;     // 16 KB
static constexpr int B_BYTES = BN * 128;     // 32 KB
static constexpr int STAGE_BYTES = A_BYTES + B_BYTES;    // 48 KB
static constexpr int SMEM_BYTES = STAGES * STAGE_BYTES;  // 192 KB

__device__ __align__(1024) __half g_Wh[(size_t)N_TOTAL * K_TOTAL];  // 32 MB
__device__ __align__(1024) __half g_Xh[(size_t)M_TOTAL * K_TOTAL];  // 64 MB

__constant__ float c_nf4[16] = {
    -1.0f, -0.6961928f, -0.52507305f, -0.3949175f, -0.28444138f, -0.18477343f,
    -0.09105004f, 0.0f, 0.0795803f, 0.1609302f, 0.2461123f, 0.33791524f,
    0.44070983f, 0.562617f, 0.72295684f, 1.0f};

// ------------------------------- helpers -----------------------------------

__device__ __forceinline__ uint32_t smem_u32(const void* p) {
  uint32_t a;
  asm("{ .reg .u64 t; cvta.to.shared.u64 t, %1; cvt.u32.u64 %0, t; }"
      : "=r"(a) : "l"(p));
  return a;
}

#define SWZ128(b) ((b) ^ (((b) >> 3) & 0x70))

#define CP_ASYNC16(dst, gsrc)                                          \
  asm volatile("cp.async.cg.shared.global [%0], [%1], 16;" ::"r"(dst), \
               "l"(gsrc)                                               \
               : "memory")
#define CP_COMMIT() asm volatile("cp.async.commit_group;" ::: "memory")
#define CP_WAIT2() asm volatile("cp.async.wait_group 2;" ::: "memory")

#define LDSM_X4(r0, r1, r2, r3, addr)                                  \
  asm volatile(                                                        \
      "ldmatrix.sync.aligned.m8n8.x4.shared.b16 {%0,%1,%2,%3}, [%4];"  \
      : "=r"(r0), "=r"(r1), "=r"(r2), "=r"(r3)                         \
      : "r"(addr))

#define MMA16816(c0, c1, c2, c3, a0, a1, a2, a3, b0, b1)               \
  asm volatile(                                                        \
      "mma.sync.aligned.m16n8k16.row.col.f32.f16.f16.f32 "             \
      "{%0,%1,%2,%3}, {%4,%5,%6,%7}, {%8,%9}, {%0,%1,%2,%3};"          \
      : "+f"(c0), "+f"(c1), "+f"(c2), "+f"(c3)                         \
      : "r"(a0), "r"(a1), "r"(a2), "r"(a3), "r"(b0), "r"(b1))

// ------------------------------ pre-kernels --------------------------------

// 4 packed int32 (16 nibbles -> 8 fp16) per thread. One scale load per
// thread (a thread's 4 ints never straddle a 2048-int output row).
__global__ void k_dequant(const int4* __restrict__ codes,
                          const float* __restrict__ scale) {
  __shared__ float cb[16];
  if (threadIdx.x < 16) cb[threadIdx.x] = c_nf4[threadIdx.x];
  __syncthreads();
  int t = blockIdx.x * blockDim.x + threadIdx.x;  // 0 .. 2097151
  int4 e = codes[t];
  float s = scale[t >> 9];  // row = (4*t) >> 11
  uint4 o;
  __half2 h;
  h = __floats2half2_rn(cb[e.x & 15] * s, cb[(e.x >> 4) & 15] * s);
  o.x = reinterpret_cast<uint32_t&>(h);
  h = __floats2half2_rn(cb[e.y & 15] * s, cb[(e.y >> 4) & 15] * s);
  o.y = reinterpret_cast<uint32_t&>(h);
  h = __floats2half2_rn(cb[e.z & 15] * s, cb[(e.z >> 4) & 15] * s);
  o.z = reinterpret_cast<uint32_t&>(h);
  h = __floats2half2_rn(cb[e.w & 15] * s, cb[(e.w >> 4) & 15] * s);
  o.w = reinterpret_cast<uint32_t&>(h);
  reinterpret_cast<uint4*>(g_Wh)[t] = o;
}

// 8 floats -> 8 halfs per thread.
__global__ void k_convert(const float4* __restrict__ x4) {
  int t = blockIdx.x * blockDim.x + threadIdx.x;  // 0 .. 4194303
  float4 v0 = x4[2 * t];
  float4 v1 = x4[2 * t + 1];
  uint4 u;
  __half2 h;
  h = __floats2half2_rn(v0.x, v0.y);
  u.x = reinterpret_cast<uint32_t&>(h);
  h = __floats2half2_rn(v0.z, v0.w);
  u.y = reinterpret_cast<uint32_t&>(h);
  h = __floats2half2_rn(v1.x, v1.y);
  u.z = reinterpret_cast<uint32_t&>(h);
  h = __floats2half2_rn(v1.z, v1.w);
  u.w = reinterpret_cast<uint32_t&>(h);
  reinterpret_cast<uint4*>(g_Xh)[t] = u;
}

// ------------------------------- GEMM kernel -------------------------------
// 256 threads = 8 warps in 2(m) x 4(n). Warp tile 64x64.
// Per k-step of 16: 4 A-ldmatrix.x4 + 4 B-ldmatrix.x4, 32 HMMA.

__global__ __launch_bounds__(256, 1) void k_gemm(const float* __restrict__ bias,
                                                 float* __restrict__ out) {
  extern __shared__ char smem[];
  const uint32_t sb = smem_u32(smem);
  const int tid = threadIdx.x;
  const int wid = tid >> 5;
  const int lid = tid & 31;
  const int wm = wid & 1;   // 0..1 -> 64-row slice
  const int wn = wid >> 1;  // 0..3 -> 64-col slice
  const int n0 = blockIdx.x * BN;
  const int m0 = blockIdx.y * BM;

  float c[4][8][4];
#pragma unroll
  for (int i = 0; i < 4; ++i)
#pragma unroll
    for (int j = 0; j < 8; ++j)
#pragma unroll
      for (int v = 0; v < 4; ++v) c[i][j][v] = 0.f;

  // ------- tile loader: 12x 16B chunks/thread (4 A + 8 B) -------
  auto load_stage = [&](int s, int kt) {
    const uint32_t stage = sb + s * STAGE_BYTES;
#pragma unroll
    for (int i = 0; i < 4; ++i) {
      const int ca = tid + 256 * i;  // 0..1023
      const int row = ca >> 3;
      const int u = ca & 7;
      const __half* src =
          g_Xh + ((size_t)(m0 + row) * K_TOTAL + kt * BK + u * 8);
      CP_ASYNC16(stage + SWZ128((uint32_t)(row * 128 + u * 16)),
                 (const void*)src);
    }
#pragma unroll
    for (int i = 0; i < 8; ++i) {
      const int cbk = tid + 256 * i;  // 0..2047
      const int row = cbk >> 3;
      const int u = cbk & 7;
      const __half* src =
          g_Wh + ((size_t)(n0 + row) * K_TOTAL + kt * BK + u * 8);
      CP_ASYNC16(stage + A_BYTES + SWZ128((uint32_t)(row * 128 + u * 16)),
                 (const void*)src);
    }
  };

  // ------- prologue: stages 0..2 in flight -------
  load_stage(0, 0);
  CP_COMMIT();
  load_stage(1, 1);
  CP_COMMIT();
  load_stage(2, 2);
  CP_COMMIT();

  // ldmatrix lane addressing
  const int a_row = wm * 64 + (lid & 15);                    // + mt*16
  const int a_kb = (lid >> 4) * 16;                          // + ks*32
  const int b_row = wn * 64 + ((lid >> 4) * 8) + (lid & 7);  // + p*16
  const int b_kb = ((lid >> 3) & 1) * 16;                    // + ks*32

  for (int kt = 0; kt < KITERS; ++kt) {
    CP_WAIT2();
    __syncthreads();
    if (kt + 3 < KITERS) load_stage((kt + 3) & (STAGES - 1), kt + 3);
    CP_COMMIT();

    const int s = kt & (STAGES - 1);
    const uint32_t aBase = sb + s * STAGE_BYTES;
    const uint32_t bBase = aBase + A_BYTES;
#pragma unroll
    for (int ks = 0; ks < 4; ++ks) {
      uint32_t a[4][4];
#pragma unroll
      for (int mt = 0; mt < 4; ++mt) {
        uint32_t off = (uint32_t)((a_row + mt * 16) * 128 + ks * 32 + a_kb);
        LDSM_X4(a[mt][0], a[mt][1], a[mt][2], a[mt][3], aBase + SWZ128(off));
      }
      uint32_t b[4][4];
#pragma unroll
      for (int p = 0; p < 4; ++p) {
        uint32_t off = (uint32_t)((b_row + p * 16) * 128 + ks * 32 + b_kb);
        LDSM_X4(b[p][0], b[p][1], b[p][2], b[p][3], bBase + SWZ128(off));
      }
#pragma unroll
      for (int mt = 0; mt < 4; ++mt)
#pragma unroll
        for (int nt = 0; nt < 8; ++nt) {
          MMA16816(c[mt][nt][0], c[mt][nt][1], c[mt][nt][2], c[mt][nt][3],
                   a[mt][0], a[mt][1], a[mt][2], a[mt][3],
                   b[nt >> 1][(nt & 1) * 2], b[nt >> 1][(nt & 1) * 2 + 1]);
        }
    }
  }

  // ------------------------------ epilogue ---------------------------------
  const int mrow = m0 + wm * 64 + (lid >> 2);
  const int ncol = n0 + wn * 64 + (lid & 3) * 2;
  float2 bias2[8];
#pragma unroll
  for (int nt = 0; nt < 8; ++nt)
    bias2[nt] = *reinterpret_cast<const float2*>(bias + ncol + nt * 8);

#pragma unroll
  for (int mt = 0; mt < 4; ++mt) {
#pragma unroll
    for (int nt = 0; nt < 8; ++nt) {
      float* p0 = out + (size_t)(mrow + mt * 16) * N_TOTAL + ncol + nt * 8;
      float* p1 = p0 + 8 * N_TOTAL;
      float2 v0 = {c[mt][nt][0] + bias2[nt].x, c[mt][nt][1] + bias2[nt].y};
      float2 v1 = {c[mt][nt][2] + bias2[nt].x, c[mt][nt][3] + bias2[nt].y};
      *reinterpret_cast<float2*>(p0) = v0;
      *reinterpret_cast<float2*>(p1) = v1;
    }
  }
}

// ------------------------------- launcher ----------------------------------

extern "C" void kernel_launch(void* const* d_in, const int* in_sizes, int n_in,
                              void* d_out, int out_size) {
  const float* x = (const float*)d_in[0];
  const int* codes = (const int*)d_in[1];
  const float* scale = (const float*)d_in[2];
  const float* bias = (const float*)d_in[3];
  float* out = (float*)d_out;

  k_dequant<<<(N_TOTAL * K_TOTAL / 8) / 256, 256>>>((const int4*)codes, scale);
  k_convert<<<(M_TOTAL * K_TOTAL / 8) / 256, 256>>>((const float4*)x);

  cudaFuncSetAttribute(k_gemm, cudaFuncAttributeMaxDynamicSharedMemorySize,
                       SMEM_BYTES);
  dim3 grid(N_TOTAL / BN, M_TOTAL / BM);  // (16, 64)
  k_gemm<<<grid, 256, SMEM_BYTES>>>(bias, out);
}

// round 4
// speedup vs baseline: 1.0444x; 1.0444x over previous
#include <cuda_runtime.h>
#include <cuda_fp16.h>
#include <cstdint>

// ---------------------------------------------------------------------------
// out[b,s,o] = sum_i x[b,s,i] * (nf4[codes][o,i] * scale[o]) + bias[o]
// M = 8192, N = 4096, K = 4096, fp32 in/out.
// Plain sm_103 target (no tcgen05) -> legacy HMMA m16n8k16 pipe.
// R4: one fused pre-kernel (dequant || convert); GEMM = 128x128 CTA with
// 4 warps of 64x64, 3 stages, 2 CTAs/SM (two decoupled pipelines per SM).
// ---------------------------------------------------------------------------

static constexpr int M_TOTAL = 8192;
static constexpr int N_TOTAL = 4096;
static constexpr int K_TOTAL = 4096;

static constexpr int BM = 128;
static constexpr int BN = 128;
static constexpr int BK = 64;            // 64 halfs = 128 B/row (SW128)
static constexpr int STAGES = 3;
static constexpr int KITERS = K_TOTAL / BK;  // 64

static constexpr int A_BYTES = BM * 128;                 // 16 KB
static constexpr int B_BYTES = BN * 128;                 // 16 KB
static constexpr int STAGE_BYTES = A_BYTES + B_BYTES;    // 32 KB
static constexpr int SMEM_BYTES = STAGES * STAGE_BYTES;  // 96 KB

__device__ __align__(1024) __half g_Wh[(size_t)N_TOTAL * K_TOTAL];  // 32 MB
__device__ __align__(1024) __half g_Xh[(size_t)M_TOTAL * K_TOTAL];  // 64 MB

__constant__ float c_nf4[16] = {
    -1.0f, -0.6961928f, -0.52507305f, -0.3949175f, -0.28444138f, -0.18477343f,
    -0.09105004f, 0.0f, 0.0795803f, 0.1609302f, 0.2461123f, 0.33791524f,
    0.44070983f, 0.562617f, 0.72295684f, 1.0f};

// ------------------------------- helpers -----------------------------------

__device__ __forceinline__ uint32_t smem_u32(const void* p) {
  uint32_t a;
  asm("{ .reg .u64 t; cvta.to.shared.u64 t, %1; cvt.u32.u64 %0, t; }"
      : "=r"(a) : "l"(p));
  return a;
}

#define SWZ128(b) ((b) ^ (((b) >> 3) & 0x70))

#define CP_ASYNC16(dst, gsrc)                                          \
  asm volatile("cp.async.cg.shared.global [%0], [%1], 16;" ::"r"(dst), \
               "l"(gsrc)                                               \
               : "memory")
#define CP_COMMIT() asm volatile("cp.async.commit_group;" ::: "memory")
#define CP_WAIT1() asm volatile("cp.async.wait_group 1;" ::: "memory")

#define LDSM_X4(r0, r1, r2, r3, addr)                                 \
  asm volatile(                                                       \
      "ldmatrix.sync.aligned.m8n8.x4.shared.b16 {%0,%1,%2,%3}, [%4];" \
      : "=r"(r0), "=r"(r1), "=r"(r2), "=r"(r3)                        \
      : "r"(addr))

#define MMA16816(c0, c1, c2, c3, a0, a1, a2, a3, b0, b1)              \
  asm volatile(                                                       \
      "mma.sync.aligned.m16n8k16.row.col.f32.f16.f16.f32 "            \
      "{%0,%1,%2,%3}, {%4,%5,%6,%7}, {%8,%9}, {%0,%1,%2,%3};"         \
      : "+f"(c0), "+f"(c1), "+f"(c2), "+f"(c3)                        \
      : "r"(a0), "r"(a1), "r"(a2), "r"(a3), "r"(b0), "r"(b1))

// ---------------------------- fused pre-kernel ------------------------------
// Blocks [0, DQ_BLOCKS): NF4 dequant (4 packed int32 -> 8 fp16 per thread).
// Blocks [DQ_BLOCKS, DQ_BLOCKS+CV_BLOCKS): x fp32 -> fp16 (8 per thread).
// One launch -> the two independent memory streams overlap.

static constexpr int DQ_BLOCKS = (N_TOTAL * K_TOTAL / 8) / 256;  // 8192
static constexpr int CV_BLOCKS = (M_TOTAL * K_TOTAL / 8) / 256;  // 16384

__global__ void k_prep(const int4* __restrict__ codes,
                       const float* __restrict__ scale,
                       const float4* __restrict__ x4) {
  if (blockIdx.x < DQ_BLOCKS) {
    __shared__ float cb[16];
    if (threadIdx.x < 16) cb[threadIdx.x] = c_nf4[threadIdx.x];
    __syncthreads();
    int t = blockIdx.x * 256 + threadIdx.x;  // 0 .. 2097151
    int4 e = codes[t];
    float s = scale[t >> 9];  // out-row = (8*t) >> 12
    uint4 o;
    __half2 h;
    h = __floats2half2_rn(cb[e.x & 15] * s, cb[(e.x >> 4) & 15] * s);
    o.x = reinterpret_cast<uint32_t&>(h);
    h = __floats2half2_rn(cb[e.y & 15] * s, cb[(e.y >> 4) & 15] * s);
    o.y = reinterpret_cast<uint32_t&>(h);
    h = __floats2half2_rn(cb[e.z & 15] * s, cb[(e.z >> 4) & 15] * s);
    o.z = reinterpret_cast<uint32_t&>(h);
    h = __floats2half2_rn(cb[e.w & 15] * s, cb[(e.w >> 4) & 15] * s);
    o.w = reinterpret_cast<uint32_t&>(h);
    reinterpret_cast<uint4*>(g_Wh)[t] = o;
  } else {
    int t = (blockIdx.x - DQ_BLOCKS) * 256 + threadIdx.x;  // 0 .. 4194303
    float4 v0 = x4[2 * t];
    float4 v1 = x4[2 * t + 1];
    uint4 u;
    __half2 h;
    h = __floats2half2_rn(v0.x, v0.y);
    u.x = reinterpret_cast<uint32_t&>(h);
    h = __floats2half2_rn(v0.z, v0.w);
    u.y = reinterpret_cast<uint32_t&>(h);
    h = __floats2half2_rn(v1.x, v1.y);
    u.z = reinterpret_cast<uint32_t&>(h);
    h = __floats2half2_rn(v1.z, v1.w);
    u.w = reinterpret_cast<uint32_t&>(h);
    reinterpret_cast<uint4*>(g_Xh)[t] = u;
  }
}

// ------------------------------- GEMM kernel -------------------------------
// 128 threads = 4 warps in 2(m) x 2(n). Warp tile 64x64. 2 CTAs/SM.

__global__ __launch_bounds__(128, 2) void k_gemm(const float* __restrict__ bias,
                                                 float* __restrict__ out) {
  extern __shared__ char smem[];
  const uint32_t sb = smem_u32(smem);
  const int tid = threadIdx.x;
  const int wid = tid >> 5;
  const int lid = tid & 31;
  const int wm = wid & 1;   // 0..1 -> 64-row slice
  const int wn = wid >> 1;  // 0..1 -> 64-col slice
  const int n0 = blockIdx.x * BN;
  const int m0 = blockIdx.y * BM;

  float c[4][8][4];
#pragma unroll
  for (int i = 0; i < 4; ++i)
#pragma unroll
    for (int j = 0; j < 8; ++j)
#pragma unroll
      for (int v = 0; v < 4; ++v) c[i][j][v] = 0.f;

  // ------- tile loader: 16x 16B chunks/thread (8 A + 8 B) -------
  auto load_stage = [&](int s, int kt) {
    const uint32_t stage = sb + s * STAGE_BYTES;
#pragma unroll
    for (int i = 0; i < 8; ++i) {
      const int ca = tid + 128 * i;  // 0..1023
      const int row = ca >> 3;
      const int u = ca & 7;
      const __half* src =
          g_Xh + ((size_t)(m0 + row) * K_TOTAL + kt * BK + u * 8);
      CP_ASYNC16(stage + SWZ128((uint32_t)(row * 128 + u * 16)),
                 (const void*)src);
    }
#pragma unroll
    for (int i = 0; i < 8; ++i) {
      const int cbk = tid + 128 * i;  // 0..1023
      const int row = cbk >> 3;
      const int u = cbk & 7;
      const __half* src =
          g_Wh + ((size_t)(n0 + row) * K_TOTAL + kt * BK + u * 8);
      CP_ASYNC16(stage + A_BYTES + SWZ128((uint32_t)(row * 128 + u * 16)),
                 (const void*)src);
    }
  };

  // ------- prologue: stages 0,1 in flight -------
  load_stage(0, 0);
  CP_COMMIT();
  load_stage(1, 1);
  CP_COMMIT();

  // ldmatrix lane addressing
  const int a_row = wm * 64 + (lid & 15);                    // + mt*16
  const int a_kb = (lid >> 4) * 16;                          // + ks*32
  const int b_row = wn * 64 + ((lid >> 4) * 8) + (lid & 7);  // + p*16
  const int b_kb = ((lid >> 3) & 1) * 16;                    // + ks*32

  for (int kt = 0; kt < KITERS; ++kt) {
    CP_WAIT1();
    __syncthreads();
    if (kt + 2 < KITERS) load_stage((kt + 2) % STAGES, kt + 2);
    CP_COMMIT();

    const int s = kt % STAGES;
    const uint32_t aBase = sb + s * STAGE_BYTES;
    const uint32_t bBase = aBase + A_BYTES;
#pragma unroll
    for (int ks = 0; ks < 4; ++ks) {
      uint32_t a[4][4];
#pragma unroll
      for (int mt = 0; mt < 4; ++mt) {
        uint32_t off = (uint32_t)((a_row + mt * 16) * 128 + ks * 32 + a_kb);
        LDSM_X4(a[mt][0], a[mt][1], a[mt][2], a[mt][3], aBase + SWZ128(off));
      }
      uint32_t b[4][4];
#pragma unroll
      for (int p = 0; p < 4; ++p) {
        uint32_t off = (uint32_t)((b_row + p * 16) * 128 + ks * 32 + b_kb);
        LDSM_X4(b[p][0], b[p][1], b[p][2], b[p][3], bBase + SWZ128(off));
      }
#pragma unroll
      for (int mt = 0; mt < 4; ++mt)
#pragma unroll
        for (int nt = 0; nt < 8; ++nt) {
          MMA16816(c[mt][nt][0], c[mt][nt][1], c[mt][nt][2], c[mt][nt][3],
                   a[mt][0], a[mt][1], a[mt][2], a[mt][3],
                   b[nt >> 1][(nt & 1) * 2], b[nt >> 1][(nt & 1) * 2 + 1]);
        }
    }
  }

  // ------------------------------ epilogue ---------------------------------
  const int mrow = m0 + wm * 64 + (lid >> 2);
  const int ncol = n0 + wn * 64 + (lid & 3) * 2;
  float2 bias2[8];
#pragma unroll
  for (int nt = 0; nt < 8; ++nt)
    bias2[nt] = *reinterpret_cast<const float2*>(bias + ncol + nt * 8);

#pragma unroll
  for (int mt = 0; mt < 4; ++mt) {
#pragma unroll
    for (int nt = 0; nt < 8; ++nt) {
      float* p0 = out + (size_t)(mrow + mt * 16) * N_TOTAL + ncol + nt * 8;
      float* p1 = p0 + 8 * N_TOTAL;
      float2 v0 = {c[mt][nt][0] + bias2[nt].x, c[mt][nt][1] + bias2[nt].y};
      float2 v1 = {c[mt][nt][2] + bias2[nt].x, c[mt][nt][3] + bias2[nt].y};
      *reinterpret_cast<float2*>(p0) = v0;
      *reinterpret_cast<float2*>(p1) = v1;
    }
  }
}

// ------------------------------- launcher ----------------------------------

extern "C" void kernel_launch(void* const* d_in, const int* in_sizes, int n_in,
                              void* d_out, int out_size) {
  const float* x = (const float*)d_in[0];
  const int* codes = (const int*)d_in[1];
  const float* scale = (const float*)d_in[2];
  const float* bias = (const float*)d_in[3];
  float* out = (float*)d_out;

  k_prep<<<DQ_BLOCKS + CV_BLOCKS, 256>>>((const int4*)codes, scale,
                                         (const float4*)x);

  cudaFuncSetAttribute(k_gemm, cudaFuncAttributeMaxDynamicSharedMemorySize,
                       SMEM_BYTES);
  dim3 grid(N_TOTAL / BN, M_TOTAL / BM);  // (32, 64)
  k_gemm<<<grid, 128, SMEM_BYTES>>>(bias, out);
}

// round 5
// speedup vs baseline: 1.1234x; 1.0756x over previous
#include <cuda_runtime.h>
#include <cuda_fp16.h>
#include <cstdint>

// ---------------------------------------------------------------------------
// out[b,s,o] = sum_i x[b,s,i] * (nf4[codes][o,i] * scale[o]) + bias[o]
// M = 8192, N = 4096, K = 4096, fp32 in/out.
// Plain sm_103 target (no tcgen05) -> legacy HMMA m16n8k16 pipe.
// R5: mbarrier-driven 3-stage pipeline (no __syncthreads / wait_group in the
// mainloop; early empty-arrive) to close the ~26% tensor-idle bubble seen in
// ncu (tensor=73.8%).
// ---------------------------------------------------------------------------

static constexpr int M_TOTAL = 8192;
static constexpr int N_TOTAL = 4096;
static constexpr int K_TOTAL = 4096;

static constexpr int BM = 128;
static constexpr int BN = 128;
static constexpr int BK = 64;            // 64 halfs = 128 B/row (SW128)
static constexpr int STAGES = 3;
static constexpr int KITERS = K_TOTAL / BK;  // 64

static constexpr int A_BYTES = BM * 128;                 // 16 KB
static constexpr int B_BYTES = BN * 128;                 // 16 KB
static constexpr int STAGE_BYTES = A_BYTES + B_BYTES;    // 32 KB
// [0,48): 6 mbarriers; stages start at 1024 (keep 1024-alignment for SW128)
static constexpr int SM_STAGE0 = 1024;
static constexpr int SMEM_BYTES = SM_STAGE0 + STAGES * STAGE_BYTES;  // 99328

__device__ __align__(1024) __half g_Wh[(size_t)N_TOTAL * K_TOTAL];  // 32 MB
__device__ __align__(1024) __half g_Xh[(size_t)M_TOTAL * K_TOTAL];  // 64 MB

__constant__ float c_nf4[16] = {
    -1.0f, -0.6961928f, -0.52507305f, -0.3949175f, -0.28444138f, -0.18477343f,
    -0.09105004f, 0.0f, 0.0795803f, 0.1609302f, 0.2461123f, 0.33791524f,
    0.44070983f, 0.562617f, 0.72295684f, 1.0f};

// ------------------------------- helpers -----------------------------------

__device__ __forceinline__ uint32_t smem_u32(const void* p) {
  uint32_t a;
  asm("{ .reg .u64 t; cvta.to.shared.u64 t, %1; cvt.u32.u64 %0, t; }"
      : "=r"(a) : "l"(p));
  return a;
}

#define SWZ128(b) ((b) ^ (((b) >> 3) & 0x70))

#define CP_ASYNC16(dst, gsrc)                                          \
  asm volatile("cp.async.cg.shared.global [%0], [%1], 16;" ::"r"(dst), \
               "l"(gsrc)                                               \
               : "memory")

#define CP_ASYNC_MBAR_ARRIVE(mbar)                                           \
  asm volatile("cp.async.mbarrier.arrive.noinc.shared::cta.b64 [%0];" ::"r"( \
                   (uint32_t)(mbar))                                         \
               : "memory")

#define MBARRIER_INIT(addr, cnt)                                             \
  asm volatile("mbarrier.init.shared.b64 [%0], %1;" ::"r"((uint32_t)(addr)), \
               "r"((uint32_t)(cnt))                                          \
               : "memory")

#define MBARRIER_ARRIVE(addr)                                     \
  asm volatile("mbarrier.arrive.shared.b64 _, [%0];" ::"r"(       \
                   (uint32_t)(addr))                              \
               : "memory")

#define MBARRIER_WAIT_PARITY(mbar_smem_addr, phase_parity)                     \
  do {                                                                         \
    uint32_t _mbar = (uint32_t)(mbar_smem_addr);                               \
    uint32_t _parity = (uint32_t)(phase_parity);                               \
    uint32_t _done;                                                            \
    asm volatile(                                                              \
        "{\n\t.reg .pred p;\n\t"                                               \
        "mbarrier.try_wait.parity.acquire.cta.shared::cta.b64 p, [%1], %2;\n\t" \
        "selp.b32 %0, 1, 0, p;\n\t}"                                           \
        : "=r"(_done)                                                          \
        : "r"(_mbar), "r"(_parity)                                             \
        : "memory");                                                           \
    if (!_done) {                                                              \
      asm volatile(                                                            \
          "{\n\t.reg .pred P1;\n\t"                                            \
          "WAIT_LOOP_%=:\n\t"                                                  \
          "mbarrier.try_wait.parity.acquire.cta.shared::cta.b64 P1, [%0], %1, 0x989680;\n\t" \
          "@P1 bra.uni WAIT_DONE_%=;\n\t"                                      \
          "bra.uni WAIT_LOOP_%=;\n\t"                                          \
          "WAIT_DONE_%=:\n\t}" ::"r"(_mbar),                                   \
          "r"(_parity)                                                         \
          : "memory");                                                         \
    }                                                                          \
  } while (0)

#define LDSM_X4(r0, r1, r2, r3, addr)                                 \
  asm volatile(                                                       \
      "ldmatrix.sync.aligned.m8n8.x4.shared.b16 {%0,%1,%2,%3}, [%4];" \
      : "=r"(r0), "=r"(r1), "=r"(r2), "=r"(r3)                        \
      : "r"(addr))

#define MMA16816(c0, c1, c2, c3, a0, a1, a2, a3, b0, b1)              \
  asm volatile(                                                       \
      "mma.sync.aligned.m16n8k16.row.col.f32.f16.f16.f32 "            \
      "{%0,%1,%2,%3}, {%4,%5,%6,%7}, {%8,%9}, {%0,%1,%2,%3};"         \
      : "+f"(c0), "+f"(c1), "+f"(c2), "+f"(c3)                        \
      : "r"(a0), "r"(a1), "r"(a2), "r"(a3), "r"(b0), "r"(b1))

// ---------------------------- fused pre-kernel ------------------------------

static constexpr int DQ_BLOCKS = (N_TOTAL * K_TOTAL / 8) / 256;  // 8192
static constexpr int CV_BLOCKS = (M_TOTAL * K_TOTAL / 8) / 256;  // 16384

__global__ void k_prep(const int4* __restrict__ codes,
                       const float* __restrict__ scale,
                       const float4* __restrict__ x4) {
  if (blockIdx.x < DQ_BLOCKS) {
    __shared__ float cb[16];
    if (threadIdx.x < 16) cb[threadIdx.x] = c_nf4[threadIdx.x];
    __syncthreads();
    int t = blockIdx.x * 256 + threadIdx.x;
    int4 e = codes[t];
    float s = scale[t >> 9];
    uint4 o;
    __half2 h;
    h = __floats2half2_rn(cb[e.x & 15] * s, cb[(e.x >> 4) & 15] * s);
    o.x = reinterpret_cast<uint32_t&>(h);
    h = __floats2half2_rn(cb[e.y & 15] * s, cb[(e.y >> 4) & 15] * s);
    o.y = reinterpret_cast<uint32_t&>(h);
    h = __floats2half2_rn(cb[e.z & 15] * s, cb[(e.z >> 4) & 15] * s);
    o.z = reinterpret_cast<uint32_t&>(h);
    h = __floats2half2_rn(cb[e.w & 15] * s, cb[(e.w >> 4) & 15] * s);
    o.w = reinterpret_cast<uint32_t&>(h);
    reinterpret_cast<uint4*>(g_Wh)[t] = o;
  } else {
    int t = (blockIdx.x - DQ_BLOCKS) * 256 + threadIdx.x;
    float4 v0 = x4[2 * t];
    float4 v1 = x4[2 * t + 1];
    uint4 u;
    __half2 h;
    h = __floats2half2_rn(v0.x, v0.y);
    u.x = reinterpret_cast<uint32_t&>(h);
    h = __floats2half2_rn(v0.z, v0.w);
    u.y = reinterpret_cast<uint32_t&>(h);
    h = __floats2half2_rn(v1.x, v1.y);
    u.z = reinterpret_cast<uint32_t&>(h);
    h = __floats2half2_rn(v1.z, v1.w);
    u.w = reinterpret_cast<uint32_t&>(h);
    reinterpret_cast<uint4*>(g_Xh)[t] = u;
  }
}

// ------------------------------- GEMM kernel -------------------------------
// 128 threads = 4 warps in 2(m) x 2(n). Warp tile 64x64. 2 CTAs/SM.
// mbarrier pipeline: full[s]=cp.async arrivals (128), empty[s]=reader arrivals.

__global__ __launch_bounds__(128, 2) void k_gemm(const float* __restrict__ bias,
                                                 float* __restrict__ out) {
  extern __shared__ char smem[];
  const uint32_t sb = smem_u32(smem);
  const int tid = threadIdx.x;
  const int wid = tid >> 5;
  const int lid = tid & 31;
  const int wm = wid & 1;
  const int wn = wid >> 1;
  const int n0 = blockIdx.x * BN;
  const int m0 = blockIdx.y * BM;

  if (tid == 0) {
#pragma unroll
    for (int s = 0; s < STAGES; ++s) {
      MBARRIER_INIT(sb + 8 * s, 128);       // full[s]
      MBARRIER_INIT(sb + 24 + 8 * s, 128);  // empty[s]
    }
  }
  __syncthreads();

  float c[4][8][4];
#pragma unroll
  for (int i = 0; i < 4; ++i)
#pragma unroll
    for (int j = 0; j < 8; ++j)
#pragma unroll
      for (int v = 0; v < 4; ++v) c[i][j][v] = 0.f;

  auto fill = [&](int s, int kt) {
    const uint32_t stage = sb + SM_STAGE0 + s * STAGE_BYTES;
#pragma unroll
    for (int i = 0; i < 8; ++i) {
      const int ca = tid + 128 * i;  // 0..1023
      const int row = ca >> 3;
      const int u = ca & 7;
      const __half* src =
          g_Xh + ((size_t)(m0 + row) * K_TOTAL + kt * BK + u * 8);
      CP_ASYNC16(stage + SWZ128((uint32_t)(row * 128 + u * 16)),
                 (const void*)src);
    }
#pragma unroll
    for (int i = 0; i < 8; ++i) {
      const int cbk = tid + 128 * i;  // 0..1023
      const int row = cbk >> 3;
      const int u = cbk & 7;
      const __half* src =
          g_Wh + ((size_t)(n0 + row) * K_TOTAL + kt * BK + u * 8);
      CP_ASYNC16(stage + A_BYTES + SWZ128((uint32_t)(row * 128 + u * 16)),
                 (const void*)src);
    }
    CP_ASYNC_MBAR_ARRIVE(sb + 8 * s);
  };

  // prologue: fill stages 0,1 (no empty-wait: stages fresh)
  fill(0, 0);
  fill(1, 1);

  // ldmatrix lane addressing
  const int a_row = wm * 64 + (lid & 15);
  const int a_kb = (lid >> 4) * 16;
  const int b_row = wn * 64 + ((lid >> 4) * 8) + (lid & 7);
  const int b_kb = ((lid >> 3) & 1) * 16;

  // pipeline cursors
  int sp = 2, pp = 1;   // produce stage/parity (first produce kp=2)
  int sc = 0, cpar = 0; // consume stage/parity

  for (int kt = 0; kt < KITERS; ++kt) {
    // -------- produce stage for kt+2 --------
    if (kt + 2 < KITERS) {
      MBARRIER_WAIT_PARITY(sb + 24 + 8 * sp, pp);
      fill(sp, kt + 2);
    }
    // -------- consume stage kt --------
    MBARRIER_WAIT_PARITY(sb + 8 * sc, cpar);
    const uint32_t aBase = sb + SM_STAGE0 + sc * STAGE_BYTES;
    const uint32_t bBase = aBase + A_BYTES;
#pragma unroll
    for (int ks = 0; ks < 4; ++ks) {
      uint32_t a[4][4];
#pragma unroll
      for (int mt = 0; mt < 4; ++mt) {
        uint32_t off = (uint32_t)((a_row + mt * 16) * 128 + ks * 32 + a_kb);
        LDSM_X4(a[mt][0], a[mt][1], a[mt][2], a[mt][3], aBase + SWZ128(off));
      }
      uint32_t b[4][4];
#pragma unroll
      for (int p = 0; p < 4; ++p) {
        uint32_t off = (uint32_t)((b_row + p * 16) * 128 + ks * 32 + b_kb);
        LDSM_X4(b[p][0], b[p][1], b[p][2], b[p][3], bBase + SWZ128(off));
      }
      if (ks == 3) {
        // all frags of this stage are in registers: release the stage early
        MBARRIER_ARRIVE(sb + 24 + 8 * sc);
      }
#pragma unroll
      for (int mt = 0; mt < 4; ++mt)
#pragma unroll
        for (int nt = 0; nt < 8; ++nt) {
          MMA16816(c[mt][nt][0], c[mt][nt][1], c[mt][nt][2], c[mt][nt][3],
                   a[mt][0], a[mt][1], a[mt][2], a[mt][3],
                   b[nt >> 1][(nt & 1) * 2], b[nt >> 1][(nt & 1) * 2 + 1]);
        }
    }
    // -------- advance cursors --------
    sp = (sp == 2) ? 0 : sp + 1;
    if (sp == 0) pp ^= 1;
    sc = (sc == 2) ? 0 : sc + 1;
    if (sc == 0) cpar ^= 1;
  }

  // ------------------------------ epilogue ---------------------------------
  const int mrow = m0 + wm * 64 + (lid >> 2);
  const int ncol = n0 + wn * 64 + (lid & 3) * 2;
  float2 bias2[8];
#pragma unroll
  for (int nt = 0; nt < 8; ++nt)
    bias2[nt] = *reinterpret_cast<const float2*>(bias + ncol + nt * 8);

#pragma unroll
  for (int mt = 0; mt < 4; ++mt) {
#pragma unroll
    for (int nt = 0; nt < 8; ++nt) {
      float* p0 = out + (size_t)(mrow + mt * 16) * N_TOTAL + ncol + nt * 8;
      float* p1 = p0 + 8 * N_TOTAL;
      float2 v0 = {c[mt][nt][0] + bias2[nt].x, c[mt][nt][1] + bias2[nt].y};
      float2 v1 = {c[mt][nt][2] + bias2[nt].x, c[mt][nt][3] + bias2[nt].y};
      *reinterpret_cast<float2*>(p0) = v0;
      *reinterpret_cast<float2*>(p1) = v1;
    }
  }
}

// ------------------------------- launcher ----------------------------------

extern "C" void kernel_launch(void* const* d_in, const int* in_sizes, int n_in,
                              void* d_out, int out_size) {
  const float* x = (const float*)d_in[0];
  const int* codes = (const int*)d_in[1];
  const float* scale = (const float*)d_in[2];
  const float* bias = (const float*)d_in[3];
  float* out = (float*)d_out;

  k_prep<<<DQ_BLOCKS + CV_BLOCKS, 256>>>((const int4*)codes, scale,
                                         (const float4*)x);

  cudaFuncSetAttribute(k_gemm, cudaFuncAttributeMaxDynamicSharedMemorySize,
                       SMEM_BYTES);
  dim3 grid(N_TOTAL / BN, M_TOTAL / BM);  // (32, 64)
  k_gemm<<<grid, 128, SMEM_BYTES>>>(bias, out);
}

// round 6
// speedup vs baseline: 1.1586x; 1.0314x over previous
#include <cuda_runtime.h>
#include <cuda_fp16.h>
#include <cstdint>

// ---------------------------------------------------------------------------
// out[b,s,o] = sum_i x[b,s,i] * (nf4[codes][o,i] * scale[o]) + bias[o]
// M = 8192, N = 4096, K = 4096, fp32 in/out.
// Plain sm_103 target (no tcgen05) -> legacy HMMA m16n8k16 pipe.
// R6: interleave cp.async fill into the ks loop (4 per ks instead of a
// 16-deep burst) + relaxed producer empty-wait. Target: tensor 79.7% -> ~88%.
// ---------------------------------------------------------------------------

static constexpr int M_TOTAL = 8192;
static constexpr int N_TOTAL = 4096;
static constexpr int K_TOTAL = 4096;

static constexpr int BM = 128;
static constexpr int BN = 128;
static constexpr int BK = 64;            // 64 halfs = 128 B/row (SW128)
static constexpr int STAGES = 3;
static constexpr int KITERS = K_TOTAL / BK;  // 64

static constexpr int A_BYTES = BM * 128;                 // 16 KB
static constexpr int B_BYTES = BN * 128;                 // 16 KB
static constexpr int STAGE_BYTES = A_BYTES + B_BYTES;    // 32 KB
static constexpr int SM_STAGE0 = 1024;
static constexpr int SMEM_BYTES = SM_STAGE0 + STAGES * STAGE_BYTES;  // 99328

__device__ __align__(1024) __half g_Wh[(size_t)N_TOTAL * K_TOTAL];  // 32 MB
__device__ __align__(1024) __half g_Xh[(size_t)M_TOTAL * K_TOTAL];  // 64 MB

__constant__ float c_nf4[16] = {
    -1.0f, -0.6961928f, -0.52507305f, -0.3949175f, -0.28444138f, -0.18477343f,
    -0.09105004f, 0.0f, 0.0795803f, 0.1609302f, 0.2461123f, 0.33791524f,
    0.44070983f, 0.562617f, 0.72295684f, 1.0f};

// ------------------------------- helpers -----------------------------------

__device__ __forceinline__ uint32_t smem_u32(const void* p) {
  uint32_t a;
  asm("{ .reg .u64 t; cvta.to.shared.u64 t, %1; cvt.u32.u64 %0, t; }"
      : "=r"(a) : "l"(p));
  return a;
}

#define SWZ128(b) ((b) ^ (((b) >> 3) & 0x70))

#define CP_ASYNC16(dst, gsrc)                                          \
  asm volatile("cp.async.cg.shared.global [%0], [%1], 16;" ::"r"(dst), \
               "l"(gsrc)                                               \
               : "memory")

#define CP_ASYNC_MBAR_ARRIVE(mbar)                                           \
  asm volatile("cp.async.mbarrier.arrive.noinc.shared::cta.b64 [%0];" ::"r"( \
                   (uint32_t)(mbar))                                         \
               : "memory")

#define MBARRIER_INIT(addr, cnt)                                             \
  asm volatile("mbarrier.init.shared.b64 [%0], %1;" ::"r"((uint32_t)(addr)), \
               "r"((uint32_t)(cnt))                                          \
               : "memory")

#define MBARRIER_ARRIVE(addr)                                     \
  asm volatile("mbarrier.arrive.shared.b64 _, [%0];" ::"r"(       \
                   (uint32_t)(addr))                              \
               : "memory")

#define MBARRIER_WAIT_PARITY(mbar_smem_addr, phase_parity)                     \
  do {                                                                         \
    uint32_t _mbar = (uint32_t)(mbar_smem_addr);                               \
    uint32_t _parity = (uint32_t)(phase_parity);                               \
    uint32_t _done;                                                            \
    asm volatile(                                                              \
        "{\n\t.reg .pred p;\n\t"                                               \
        "mbarrier.try_wait.parity.acquire.cta.shared::cta.b64 p, [%1], %2;\n\t" \
        "selp.b32 %0, 1, 0, p;\n\t}"                                           \
        : "=r"(_done)                                                          \
        : "r"(_mbar), "r"(_parity)                                             \
        : "memory");                                                           \
    if (!_done) {                                                              \
      asm volatile(                                                            \
          "{\n\t.reg .pred P1;\n\t"                                            \
          "WAIT_LOOP_%=:\n\t"                                                  \
          "mbarrier.try_wait.parity.acquire.cta.shared::cta.b64 P1, [%0], %1, 0x989680;\n\t" \
          "@P1 bra.uni WAIT_DONE_%=;\n\t"                                      \
          "bra.uni WAIT_LOOP_%=;\n\t"                                          \
          "WAIT_DONE_%=:\n\t}" ::"r"(_mbar),                                   \
          "r"(_parity)                                                         \
          : "memory");                                                         \
    }                                                                          \
  } while (0)

// Producer-side wait: post-wait writes are cp.async (async proxy) -> relaxed.
#define MBARRIER_WAIT_PARITY_RELAXED(mbar_smem_addr, phase_parity)             \
  do {                                                                         \
    uint32_t _mbar = (uint32_t)(mbar_smem_addr);                               \
    uint32_t _parity = (uint32_t)(phase_parity);                               \
    uint32_t _done;                                                            \
    asm volatile(                                                              \
        "{\n\t.reg .pred p;\n\t"                                               \
        "mbarrier.try_wait.parity.relaxed.cta.shared::cta.b64 p, [%1], %2;\n\t" \
        "selp.b32 %0, 1, 0, p;\n\t}"                                           \
        : "=r"(_done)                                                          \
        : "r"(_mbar), "r"(_parity)                                             \
        : "memory");                                                           \
    if (!_done) {                                                              \
      asm volatile(                                                            \
          "{\n\t.reg .pred P1;\n\t"                                            \
          "WAIT_LOOP_%=:\n\t"                                                  \
          "mbarrier.try_wait.parity.relaxed.cta.shared::cta.b64 P1, [%0], %1, 0x989680;\n\t" \
          "@P1 bra.uni WAIT_DONE_%=;\n\t"                                      \
          "bra.uni WAIT_LOOP_%=;\n\t"                                          \
          "WAIT_DONE_%=:\n\t}" ::"r"(_mbar),                                   \
          "r"(_parity)                                                         \
          : "memory");                                                         \
    }                                                                          \
  } while (0)

#define LDSM_X4(r0, r1, r2, r3, addr)                                 \
  asm volatile(                                                       \
      "ldmatrix.sync.aligned.m8n8.x4.shared.b16 {%0,%1,%2,%3}, [%4];" \
      : "=r"(r0), "=r"(r1), "=r"(r2), "=r"(r3)                        \
      : "r"(addr))

#define MMA16816(c0, c1, c2, c3, a0, a1, a2, a3, b0, b1)              \
  asm volatile(                                                       \
      "mma.sync.aligned.m16n8k16.row.col.f32.f16.f16.f32 "            \
      "{%0,%1,%2,%3}, {%4,%5,%6,%7}, {%8,%9}, {%0,%1,%2,%3};"         \
      : "+f"(c0), "+f"(c1), "+f"(c2), "+f"(c3)                        \
      : "r"(a0), "r"(a1), "r"(a2), "r"(a3), "r"(b0), "r"(b1))

// ---------------------------- fused pre-kernel ------------------------------

static constexpr int DQ_BLOCKS = (N_TOTAL * K_TOTAL / 8) / 256;  // 8192
static constexpr int CV_BLOCKS = (M_TOTAL * K_TOTAL / 8) / 256;  // 16384

__global__ void k_prep(const int4* __restrict__ codes,
                       const float* __restrict__ scale,
                       const float4* __restrict__ x4) {
  if (blockIdx.x < DQ_BLOCKS) {
    __shared__ float cb[16];
    if (threadIdx.x < 16) cb[threadIdx.x] = c_nf4[threadIdx.x];
    __syncthreads();
    int t = blockIdx.x * 256 + threadIdx.x;
    int4 e = codes[t];
    float s = scale[t >> 9];
    uint4 o;
    __half2 h;
    h = __floats2half2_rn(cb[e.x & 15] * s, cb[(e.x >> 4) & 15] * s);
    o.x = reinterpret_cast<uint32_t&>(h);
    h = __floats2half2_rn(cb[e.y & 15] * s, cb[(e.y >> 4) & 15] * s);
    o.y = reinterpret_cast<uint32_t&>(h);
    h = __floats2half2_rn(cb[e.z & 15] * s, cb[(e.z >> 4) & 15] * s);
    o.z = reinterpret_cast<uint32_t&>(h);
    h = __floats2half2_rn(cb[e.w & 15] * s, cb[(e.w >> 4) & 15] * s);
    o.w = reinterpret_cast<uint32_t&>(h);
    reinterpret_cast<uint4*>(g_Wh)[t] = o;
  } else {
    int t = (blockIdx.x - DQ_BLOCKS) * 256 + threadIdx.x;
    float4 v0 = x4[2 * t];
    float4 v1 = x4[2 * t + 1];
    uint4 u;
    __half2 h;
    h = __floats2half2_rn(v0.x, v0.y);
    u.x = reinterpret_cast<uint32_t&>(h);
    h = __floats2half2_rn(v0.z, v0.w);
    u.y = reinterpret_cast<uint32_t&>(h);
    h = __floats2half2_rn(v1.x, v1.y);
    u.z = reinterpret_cast<uint32_t&>(h);
    h = __floats2half2_rn(v1.z, v1.w);
    u.w = reinterpret_cast<uint32_t&>(h);
    reinterpret_cast<uint4*>(g_Xh)[t] = u;
  }
}

// ------------------------------- GEMM kernel -------------------------------
// 128 threads = 4 warps in 2(m) x 2(n). Warp tile 64x64. 2 CTAs/SM.
// mbarrier pipeline; fill for kt+2 interleaved 4-chunks-per-ks into kt's
// consume loop.

__global__ __launch_bounds__(128, 2) void k_gemm(const float* __restrict__ bias,
                                                 float* __restrict__ out) {
  extern __shared__ char smem[];
  const uint32_t sb = smem_u32(smem);
  const int tid = threadIdx.x;
  const int wid = tid >> 5;
  const int lid = tid & 31;
  const int wm = wid & 1;
  const int wn = wid >> 1;
  const int n0 = blockIdx.x * BN;
  const int m0 = blockIdx.y * BM;

  if (tid == 0) {
#pragma unroll
    for (int s = 0; s < STAGES; ++s) {
      MBARRIER_INIT(sb + 8 * s, 128);       // full[s]
      MBARRIER_INIT(sb + 24 + 8 * s, 128);  // empty[s]
    }
  }
  __syncthreads();

  float c[4][8][4];
#pragma unroll
  for (int i = 0; i < 4; ++i)
#pragma unroll
    for (int j = 0; j < 8; ++j)
#pragma unroll
      for (int v = 0; v < 4; ++v) c[i][j][v] = 0.f;

  // Per-thread base addresses for the fill (row/col constant per thread).
  const int f_row = tid >> 3;      // 0..15 (+16 per chunk pair step of 2)
  const int f_u = tid & 7;
  // chunk i covers row f_row + 16*i
  const __half* aSrc0 = g_Xh + ((size_t)(m0 + f_row) * K_TOTAL + f_u * 8);
  const __half* bSrc0 = g_Wh + ((size_t)(n0 + f_row) * K_TOTAL + f_u * 8);

  // issue 2 A-chunks + 2 B-chunks (part = 0..3) of stage s for k-iter kt
  auto fill_part = [&](int s, int kt, int part) {
    const uint32_t stage = sb + SM_STAGE0 + s * STAGE_BYTES;
    const size_t kOff = (size_t)kt * BK;
#pragma unroll
    for (int j = 0; j < 2; ++j) {
      const int i = part * 2 + j;  // 0..7
      const int row = f_row + 16 * i;
      CP_ASYNC16(stage + SWZ128((uint32_t)(row * 128 + f_u * 16)),
                 (const void*)(aSrc0 + kOff + (size_t)16 * i * K_TOTAL));
    }
#pragma unroll
    for (int j = 0; j < 2; ++j) {
      const int i = part * 2 + j;
      const int row = f_row + 16 * i;
      CP_ASYNC16(stage + A_BYTES + SWZ128((uint32_t)(row * 128 + f_u * 16)),
                 (const void*)(bSrc0 + kOff + (size_t)16 * i * K_TOTAL));
    }
  };

  // prologue: fill stages 0,1 completely
#pragma unroll
  for (int p = 0; p < 4; ++p) fill_part(0, 0, p);
  CP_ASYNC_MBAR_ARRIVE(sb + 8 * 0);
#pragma unroll
  for (int p = 0; p < 4; ++p) fill_part(1, 1, p);
  CP_ASYNC_MBAR_ARRIVE(sb + 8 * 1);

  // ldmatrix lane addressing
  const int a_row = wm * 64 + (lid & 15);
  const int a_kb = (lid >> 4) * 16;
  const int b_row = wn * 64 + ((lid >> 4) * 8) + (lid & 7);
  const int b_kb = ((lid >> 3) & 1) * 16;

  int sp = 2, pp = 1;    // produce stage/parity
  int sc = 0, cpar = 0;  // consume stage/parity

  for (int kt = 0; kt < KITERS; ++kt) {
    const bool produce = (kt + 2 < KITERS);
    MBARRIER_WAIT_PARITY(sb + 8 * sc, cpar);
    const uint32_t aBase = sb + SM_STAGE0 + sc * STAGE_BYTES;
    const uint32_t bBase = aBase + A_BYTES;
#pragma unroll
    for (int ks = 0; ks < 4; ++ks) {
      uint32_t a[4][4];
#pragma unroll
      for (int mt = 0; mt < 4; ++mt) {
        uint32_t off = (uint32_t)((a_row + mt * 16) * 128 + ks * 32 + a_kb);
        LDSM_X4(a[mt][0], a[mt][1], a[mt][2], a[mt][3], aBase + SWZ128(off));
      }
      uint32_t b[4][4];
#pragma unroll
      for (int p = 0; p < 4; ++p) {
        uint32_t off = (uint32_t)((b_row + p * 16) * 128 + ks * 32 + b_kb);
        LDSM_X4(b[p][0], b[p][1], b[p][2], b[p][3], bBase + SWZ128(off));
      }
      if (produce) {
        if (ks == 0) MBARRIER_WAIT_PARITY_RELAXED(sb + 24 + 8 * sp, pp);
        fill_part(sp, kt + 2, ks);
      }
      if (ks == 3) {
        MBARRIER_ARRIVE(sb + 24 + 8 * sc);            // release consumed stage
        if (produce) CP_ASYNC_MBAR_ARRIVE(sb + 8 * sp);  // seal produced stage
      }
#pragma unroll
      for (int mt = 0; mt < 4; ++mt)
#pragma unroll
        for (int nt = 0; nt < 8; ++nt) {
          MMA16816(c[mt][nt][0], c[mt][nt][1], c[mt][nt][2], c[mt][nt][3],
                   a[mt][0], a[mt][1], a[mt][2], a[mt][3],
                   b[nt >> 1][(nt & 1) * 2], b[nt >> 1][(nt & 1) * 2 + 1]);
        }
    }
    sp = (sp == 2) ? 0 : sp + 1;
    if (sp == 0) pp ^= 1;
    sc = (sc == 2) ? 0 : sc + 1;
    if (sc == 0) cpar ^= 1;
  }

  // ------------------------------ epilogue ---------------------------------
  const int mrow = m0 + wm * 64 + (lid >> 2);
  const int ncol = n0 + wn * 64 + (lid & 3) * 2;
  float2 bias2[8];
#pragma unroll
  for (int nt = 0; nt < 8; ++nt)
    bias2[nt] = *reinterpret_cast<const float2*>(bias + ncol + nt * 8);

#pragma unroll
  for (int mt = 0; mt < 4; ++mt) {
#pragma unroll
    for (int nt = 0; nt < 8; ++nt) {
      float* p0 = out + (size_t)(mrow + mt * 16) * N_TOTAL + ncol + nt * 8;
      float* p1 = p0 + 8 * N_TOTAL;
      float2 v0 = {c[mt][nt][0] + bias2[nt].x, c[mt][nt][1] + bias2[nt].y};
      float2 v1 = {c[mt][nt][2] + bias2[nt].x, c[mt][nt][3] + bias2[nt].y};
      *reinterpret_cast<float2*>(p0) = v0;
      *reinterpret_cast<float2*>(p1) = v1;
    }
  }
}

// ------------------------------- launcher ----------------------------------

extern "C" void kernel_launch(void* const* d_in, const int* in_sizes, int n_in,
                              void* d_out, int out_size) {
  const float* x = (const float*)d_in[0];
  const int* codes = (const int*)d_in[1];
  const float* scale = (const float*)d_in[2];
  const float* bias = (const float*)d_in[3];
  float* out = (float*)d_out;

  k_prep<<<DQ_BLOCKS + CV_BLOCKS, 256>>>((const int4*)codes, scale,
                                         (const float4*)x);

  cudaFuncSetAttribute(k_gemm, cudaFuncAttributeMaxDynamicSharedMemorySize,
                       SMEM_BYTES);
  dim3 grid(N_TOTAL / BN, M_TOTAL / BM);  // (32, 64)
  k_gemm<<<grid, 128, SMEM_BYTES>>>(bias, out);
}